// round 15
// baseline (speedup 1.0000x reference)
#include <cuda_runtime.h>
#include <math.h>
#include <stdint.h>

#define NN   8192
#define FIN  256
#define NH   4
#define ND   64
#define HD   256

// ---------------- device scratch (allocation-free contract) ----------------
__device__ float g_hT [NH * ND * NN];                  // projected features: [h][d][n]
// B operand in per-lane mma-fragment order:
// g_hF[h][chunk][kp(4)][sub(2)][nt(8)][lane(32)][2]  (tf32-rounded)
__device__ __align__(16) float g_hF[NH * 128 * 4096];
__device__ float g_nsl[NH * NN];                       // -score_l
__device__ float g_q  [NH * NN];                       // exp(0.8 * score_l)
__device__ __align__(16) float g_sr [NH * NN];
__device__ __align__(16) float g_er [NH * NN];
__device__ __align__(16) float g_er2[NH * NN];
__device__ unsigned int g_keep[NN * 256 + 512];        // keep bitmask, diag folded

// ---------------- helpers ----------------
__device__ __forceinline__ float tf32r(float x) {
    unsigned int u;
    asm("cvt.rna.tf32.f32 %0, %1;" : "=r"(u) : "f"(x));
    return __uint_as_float(u);
}
__device__ __forceinline__ void mma_tf32(float* c, const unsigned int* a,
                                         unsigned int b0, unsigned int b1) {
    asm volatile("mma.sync.aligned.m16n8k8.row.col.f32.tf32.tf32.f32 "
                 "{%0,%1,%2,%3}, {%4,%5,%6,%7}, {%8,%9}, {%0,%1,%2,%3};"
                 : "+f"(c[0]), "+f"(c[1]), "+f"(c[2]), "+f"(c[3])
                 : "r"(a[0]), "r"(a[1]), "r"(a[2]), "r"(a[3]), "r"(b0), "r"(b1));
}

// ---------------- Kernel 1: h = x @ W ; writes g_hT and fragment-ordered g_hF --
__global__ __launch_bounds__(256) void k_proj(const float* __restrict__ A,
                                              const float* __restrict__ B) {
    __shared__ float As[64 * 17];
    __shared__ float Bs[16 * 64];
    __shared__ float Tb[64 * 68];
    const int t  = threadIdx.x;
    const int ty = t >> 4, tx = t & 15;
    const int row0 = blockIdx.y * 64, col0 = blockIdx.x * 64;
    float acc[4][4] = {};
    for (int k0 = 0; k0 < FIN; k0 += 16) {
        #pragma unroll
        for (int l = 0; l < 4; ++l) {
            int idx = t + l * 256;
            int m = idx >> 4, k = idx & 15;
            As[m * 17 + k] = A[(size_t)(row0 + m) * FIN + k0 + k];
            int kb = idx >> 6, n = idx & 63;
            Bs[kb * 64 + n] = B[(size_t)(k0 + kb) * HD + col0 + n];
        }
        __syncthreads();
        #pragma unroll
        for (int k = 0; k < 16; ++k) {
            float a0 = As[(ty * 4 + 0) * 17 + k];
            float a1 = As[(ty * 4 + 1) * 17 + k];
            float a2 = As[(ty * 4 + 2) * 17 + k];
            float a3 = As[(ty * 4 + 3) * 17 + k];
            float4 b = *(const float4*)&Bs[k * 64 + tx * 4];
            acc[0][0] += a0 * b.x; acc[0][1] += a0 * b.y; acc[0][2] += a0 * b.z; acc[0][3] += a0 * b.w;
            acc[1][0] += a1 * b.x; acc[1][1] += a1 * b.y; acc[1][2] += a1 * b.z; acc[1][3] += a1 * b.w;
            acc[2][0] += a2 * b.x; acc[2][1] += a2 * b.y; acc[2][2] += a2 * b.z; acc[2][3] += a2 * b.w;
            acc[3][0] += a3 * b.x; acc[3][1] += a3 * b.y; acc[3][2] += a3 * b.z; acc[3][3] += a3 * b.w;
        }
        __syncthreads();
    }
    // transpose: Tb[feature][node]
    #pragma unroll
    for (int i = 0; i < 4; ++i)
        #pragma unroll
        for (int j = 0; j < 4; ++j)
            Tb[(tx * 4 + j) * 68 + (ty * 4 + i)] = acc[i][j];
    __syncthreads();
    // exact features for k_scores
    {
        const int c = t >> 2, q = t & 3;
        #pragma unroll
        for (int m = 0; m < 4; ++m) {
            float4 v = *(const float4*)&Tb[c * 68 + q * 16 + m * 4];
            *(float4*)(g_hT + (size_t)(col0 + c) * NN + row0 + q * 16 + m * 4) = v;
        }
    }
    // fragment-ordered tf32 B tile: this block IS tile (head = col0/64, chunk = row0/64)
    // value(kp,sub,nt,l,e) = Tb[n*68 + j], n = nt*8 + (l>>2),
    //   kf = kp*16 + sub*8 + e*4 + (l&3), j = 16*(kf&3) + (kf>>2)
    {
        const int hh = col0 >> 6, cc = row0 >> 6;
        float* dst = g_hF + ((size_t)hh * 128 + cc) * 4096;
        #pragma unroll
        for (int i = 0; i < 4; ++i) {
            const int o  = t * 4 + i;          // float4 index 0..1023
            const int g  = o * 4;              // float index
            const int l0 = (g >> 1) & 31;      // even lane
            const int nt = (g >> 6) & 7;
            const int sub = (g >> 9) & 1;
            const int kp  = g >> 10;
            float vals[4];
            #pragma unroll
            for (int u = 0; u < 2; ++u) {
                const int l = l0 + u;
                const int n = nt * 8 + (l >> 2);
                #pragma unroll
                for (int e = 0; e < 2; ++e) {
                    const int kf = kp * 16 + sub * 8 + e * 4 + (l & 3);
                    const int j  = 16 * (kf & 3) + (kf >> 2);
                    vals[u * 2 + e] = tf32r(Tb[n * 68 + j]);
                }
            }
            *(float4*)(dst + g) = make_float4(vals[0], vals[1], vals[2], vals[3]);
        }
    }
}

// ---------------- Kernel 2: per-(node, head) scores + exp factors ----------------
__global__ __launch_bounds__(256) void k_scores(const float* __restrict__ a_l,
                                                const float* __restrict__ a_r) {
    __shared__ float alS[HD], arS[HD];
    const int t = threadIdx.x;
    if (t < HD) { alS[t] = a_l[t]; arS[t] = a_r[t]; }
    __syncthreads();
    const int n = blockIdx.x * 256 + t;
    #pragma unroll
    for (int h = 0; h < NH; ++h) {
        float sl = 0.f, sr = 0.f;
        #pragma unroll 8
        for (int d = 0; d < ND; ++d) {
            float v = g_hT[(size_t)(h * ND + d) * NN + n];
            sl += v * alS[h * ND + d];
            sr += v * arS[h * ND + d];
        }
        const int idx = h * NN + n;
        g_nsl[idx] = -sl;
        g_q  [idx] = expf(0.8f * sl);
        g_sr [idx] = sr;
        g_er [idx] = expf(sr);
        g_er2[idx] = expf(0.2f * sr);
    }
}

// ---------------- Kernel 2b: pack (adj + eye) != 0 into bitmask, MLP=8 ----------
__global__ __launch_bounds__(256) void k_pack(const int* __restrict__ adj) {
    const int lane = threadIdx.x & 31;
    const int gw   = (blockIdx.x * 256 + threadIdx.x) >> 5;
    const int nw   = (gridDim.x * 256) >> 5;
    for (int t = gw * 8; t < NN * 256; t += nw * 8) {
        const int* p = adj + (size_t)t * 32 + lane;
        int v[8];
        #pragma unroll
        for (int u = 0; u < 8; ++u) v[u] = p[u * 32];
        unsigned int b[8];
        #pragma unroll
        for (int u = 0; u < 8; ++u) b[u] = __ballot_sync(0xffffffffu, v[u] != 0);
        if (lane == 0) {
            #pragma unroll
            for (int u = 0; u < 8; ++u) {
                const int w = t + u, row = w >> 8, c = w & 255;
                if ((row >> 5) == c) b[u] |= 1u << (row & 31);
            }
            *(uint4*)(g_keep + t)     = make_uint4(b[0], b[1], b[2], b[3]);
            *(uint4*)(g_keep + t + 4) = make_uint4(b[4], b[5], b[6], b[7]);
        }
    }
}

// ---------------- Kernel 3: fused aggregation, 16 warps x 16 rows, barrier-free -
// 512 threads = 16 warps; warp wm owns rows [wm*16, wm*16+16) x all 64 N cols.
// Splits R14's two per-warp m16 fragments across warp pairs -> per-thread regs
// halve, occupancy doubles to 4 warps/SMSP. Arithmetic bit-identical to R14.
__global__ __launch_bounds__(512, 1) void k_gat(float* __restrict__ out) {
    const int tid  = threadIdx.x;
    const int lane = tid & 31;
    const int wm   = tid >> 5;        // 0..15 (m16 tile)
    const int h    = blockIdx.x;
    const int i0   = blockIdx.y * 256;
    const int q    = lane & 3;
    const int rl   = lane >> 2;
    const unsigned int ONE = 0x3F800000u;   // 1.0f (exact in tf32)

    // rows this lane generates weights for: p in {0,1} -> row wm*16 + p*8 + rl
    float nslR[2], qR[2];
    int growL[2];
    #pragma unroll
    for (int p = 0; p < 2; ++p) {
        growL[p] = i0 + wm * 16 + p * 8 + rl;
        nslR[p] = g_nsl[h * NN + growL[p]];
        qR[p]   = g_q  [h * NN + growL[p]];
    }
    const unsigned int shift = (unsigned int)((q & 1) * 16);

    const float* fF   = g_hF + (size_t)h * 128 * 4096;
    const float* erG  = g_er  + h * NN;
    const float* er2G = g_er2 + h * NN;
    const float* srG  = g_sr  + h * NN;

    float acc[8][4];
    #pragma unroll
    for (int nt = 0; nt < 8; ++nt)
        #pragma unroll
        for (int c = 0; c < 4; ++c) acc[nt][c] = 0.f;
    float accD[4];
    #pragma unroll
    for (int c = 0; c < 4; ++c) accD[c] = 0.f;

    for (int jt = 0; jt < 128; ++jt) {
        const float* fC = fF + (size_t)jt * 4096;

        // keep words for this chunk
        unsigned int kw[2];
        #pragma unroll
        for (int p = 0; p < 2; ++p)
            kw[p] = g_keep[(size_t)growL[p] * 256 + jt * 2 + (q >> 1)] >> shift;

        #pragma unroll
        for (int kp = 0; kp < 4; ++kp) {
            // B fragments: 16 coalesced LDG.64 (L1-shared across warps)
            float2 bf[2][8];
            #pragma unroll
            for (int sub = 0; sub < 2; ++sub)
                #pragma unroll
                for (int nt = 0; nt < 8; ++nt)
                    bf[sub][nt] = *(const float2*)(fC + ((kp * 2 + sub) * 8 + nt) * 64 + lane * 2);

            const float4 er4  = *(const float4*)(erG  + jt * 64 + q * 16 + kp * 4);
            const float4 er24 = *(const float4*)(er2G + jt * 64 + q * 16 + kp * 4);
            const float4 sr4  = *(const float4*)(srG  + jt * 64 + q * 16 + kp * 4);

            #pragma unroll
            for (int sub = 0; sub < 2; ++sub) {
                const int s = kp * 2 + sub;
                const float ex  = sub ? er4.z  : er4.x;
                const float ey  = sub ? er4.w  : er4.y;
                const float e2x = sub ? er24.z : er24.x;
                const float e2y = sub ? er24.w : er24.y;
                const float sx  = sub ? sr4.z  : sr4.x;
                const float sy  = sub ? sr4.w  : sr4.y;
                unsigned int a[4];
                #pragma unroll
                for (int p = 0; p < 2; ++p) {
                    const unsigned int bits = (kw[p] >> (2 * s)) & 3u;
                    float w0 = (sx > nslR[p]) ? qR[p] * ex : e2x;
                    float w1 = (sy > nslR[p]) ? qR[p] * ey : e2y;
                    w0 = (bits & 1u) ? w0 : 0.f;
                    w1 = (bits & 2u) ? w1 : 0.f;
                    a[p]     = __float_as_uint(w0);
                    a[p + 2] = __float_as_uint(w1);
                }
                #pragma unroll
                for (int nt = 0; nt < 8; ++nt)
                    mma_tf32(acc[nt], a,
                             __float_as_uint(bf[sub][nt].x),
                             __float_as_uint(bf[sub][nt].y));
                mma_tf32(accD, a, ONE, ONE);   // denominator row-sums
            }
        }
    }

    // ---- epilogue: normalize + store (denominators already per-row in accD) ----
    const int r0 = i0 + wm * 16 + rl;
    const float inv0 = 1.0f / accD[0];    // row wm*16 + rl
    const float inv1 = 1.0f / accD[2];    // row wm*16 + rl + 8
    #pragma unroll
    for (int nt = 0; nt < 8; ++nt) {
        const int c = h * ND + nt * 8 + q * 2;
        float2 v0 = make_float2(acc[nt][0] * inv0, acc[nt][1] * inv0);
        float2 v1 = make_float2(acc[nt][2] * inv1, acc[nt][3] * inv1);
        *(float2*)(out + (size_t)r0 * HD + c)       = v0;
        *(float2*)(out + (size_t)(r0 + 8) * HD + c) = v1;
    }
}

// ---------------- launch ----------------
extern "C" void kernel_launch(void* const* d_in, const int* in_sizes, int n_in,
                              void* d_out, int out_size) {
    const float* x   = (const float*)d_in[0];
    const int*   adj = (const int*)  d_in[1];
    const float* W   = (const float*)d_in[2];
    const float* a_l = (const float*)d_in[3];
    const float* a_r = (const float*)d_in[4];
    float* out = (float*)d_out;

    k_pack<<<1184, 256>>>(adj);
    k_proj<<<dim3(HD / 64, NN / 64), 256>>>(x, W);
    k_scores<<<NN / 256, 256>>>(a_l, a_r);

    k_gat<<<dim3(NH, NN / 256), 512>>>(out);
}

// round 16
// speedup vs baseline: 1.1946x; 1.1946x over previous
#include <cuda_runtime.h>
#include <math.h>
#include <stdint.h>

#define NN   8192
#define FIN  256
#define NH   4
#define ND   64
#define HD   256

// ---------------- device scratch (allocation-free contract) ----------------
// B operand in per-lane mma-fragment order, nt-paired for LDG.128:
// g_hF[h][chunk][kp(4)][sub(2)][nt2(4)][lane(32)][4]   (tf32-rounded)
//   float e4 of lane l: ntp=e4>>1, e=e4&1, nt=nt2*2+ntp, n=nt*8+(l>>2),
//   kf=kp*16+sub*8+e*4+(l&3), j=16*(kf&3)+(kf>>2)
__device__ __align__(16) float g_hF[NH * 128 * 4096];
__device__ float g_nsl[NH * NN];                       // -score_l
__device__ float g_q  [NH * NN];                       // exp(0.8 * score_l)
__device__ __align__(16) float g_sr [NH * NN];
__device__ __align__(16) float g_er [NH * NN];
__device__ __align__(16) float g_er2[NH * NN];
__device__ unsigned int g_keep[NN * 256 + 512];        // keep bitmask, diag folded

// ---------------- helpers ----------------
__device__ __forceinline__ float tf32r(float x) {
    unsigned int u;
    asm("cvt.rna.tf32.f32 %0, %1;" : "=r"(u) : "f"(x));
    return __uint_as_float(u);
}
__device__ __forceinline__ void mma_tf32(float* c, const unsigned int* a,
                                         unsigned int b0, unsigned int b1) {
    asm volatile("mma.sync.aligned.m16n8k8.row.col.f32.tf32.tf32.f32 "
                 "{%0,%1,%2,%3}, {%4,%5,%6,%7}, {%8,%9}, {%0,%1,%2,%3};"
                 : "+f"(c[0]), "+f"(c[1]), "+f"(c[2]), "+f"(c[3])
                 : "r"(a[0]), "r"(a[1]), "r"(a[2]), "r"(a[3]), "r"(b0), "r"(b1));
}

// ---------------- Kernel 1: h = x @ W ; fused scores + fragment-ordered g_hF ----
// block (hh, rowblock): computes h[row0..row0+63][head hh * 64 dims], then
// (a) scores/exp factors from the exact accumulators, (b) tf32 B fragments.
__global__ __launch_bounds__(256) void k_proj(const float* __restrict__ A,
                                              const float* __restrict__ B,
                                              const float* __restrict__ a_l,
                                              const float* __restrict__ a_r) {
    __shared__ float As[64 * 17];
    __shared__ float Bs[16 * 64];
    __shared__ float Tb[64 * 68];
    __shared__ float alS[64], arS[64];
    const int t  = threadIdx.x;
    const int ty = t >> 4, tx = t & 15;
    const int hh   = blockIdx.x;
    const int row0 = blockIdx.y * 64;
    const int col0 = hh * 64;

    if (t < 64)       alS[t]      = a_l[col0 + t];
    else if (t < 128) arS[t - 64] = a_r[col0 + t - 64];

    float acc[4][4] = {};
    for (int k0 = 0; k0 < FIN; k0 += 16) {
        #pragma unroll
        for (int l = 0; l < 4; ++l) {
            int idx = t + l * 256;
            int m = idx >> 4, k = idx & 15;
            As[m * 17 + k] = A[(size_t)(row0 + m) * FIN + k0 + k];
            int kb = idx >> 6, n = idx & 63;
            Bs[kb * 64 + n] = B[(size_t)(k0 + kb) * HD + col0 + n];
        }
        __syncthreads();
        #pragma unroll
        for (int k = 0; k < 16; ++k) {
            float a0 = As[(ty * 4 + 0) * 17 + k];
            float a1 = As[(ty * 4 + 1) * 17 + k];
            float a2 = As[(ty * 4 + 2) * 17 + k];
            float a3 = As[(ty * 4 + 3) * 17 + k];
            float4 b = *(const float4*)&Bs[k * 64 + tx * 4];
            acc[0][0] += a0 * b.x; acc[0][1] += a0 * b.y; acc[0][2] += a0 * b.z; acc[0][3] += a0 * b.w;
            acc[1][0] += a1 * b.x; acc[1][1] += a1 * b.y; acc[1][2] += a1 * b.z; acc[1][3] += a1 * b.w;
            acc[2][0] += a2 * b.x; acc[2][1] += a2 * b.y; acc[2][2] += a2 * b.z; acc[2][3] += a2 * b.w;
            acc[3][0] += a3 * b.x; acc[3][1] += a3 * b.y; acc[3][2] += a3 * b.z; acc[3][3] += a3 * b.w;
        }
        __syncthreads();
    }
    // transpose: Tb[feature][node]
    #pragma unroll
    for (int i = 0; i < 4; ++i)
        #pragma unroll
        for (int j = 0; j < 4; ++j)
            Tb[(tx * 4 + j) * 68 + (ty * 4 + i)] = acc[i][j];
    __syncthreads();

    // ---- fused scores: sl/sr per node from exact Tb; 4 threads per node ----
    {
        const int node = t >> 2, part = t & 3;
        float sl = 0.f, sr = 0.f;
        #pragma unroll
        for (int d = 0; d < 16; ++d) {
            const float v = Tb[(part * 16 + d) * 68 + node];
            sl += v * alS[part * 16 + d];
            sr += v * arS[part * 16 + d];
        }
        sl += __shfl_xor_sync(0xffffffffu, sl, 1);
        sl += __shfl_xor_sync(0xffffffffu, sl, 2);
        sr += __shfl_xor_sync(0xffffffffu, sr, 1);
        sr += __shfl_xor_sync(0xffffffffu, sr, 2);
        if (part == 0) {
            const int idx = hh * NN + row0 + node;
            g_nsl[idx] = -sl;
            g_q  [idx] = expf(0.8f * sl);
            g_sr [idx] = sr;
            g_er [idx] = expf(sr);
            g_er2[idx] = expf(0.2f * sr);
        }
    }

    // ---- fragment-ordered tf32 B tile (nt-paired for LDG.128) ----
    {
        const int cc = row0 >> 6;
        float* dst = g_hF + ((size_t)hh * 128 + cc) * 4096;
        #pragma unroll
        for (int i = 0; i < 4; ++i) {
            const int o    = t * 4 + i;        // float4 index 0..1023
            const int g    = o * 4;            // float index
            const int lane = o & 31;
            const int nt2  = (g >> 7) & 3;
            const int sub  = (g >> 9) & 1;
            const int kp   = g >> 10;
            float vals[4];
            #pragma unroll
            for (int e4 = 0; e4 < 4; ++e4) {
                const int ntp = e4 >> 1, e = e4 & 1;
                const int n  = (nt2 * 2 + ntp) * 8 + (lane >> 2);
                const int kf = kp * 16 + sub * 8 + e * 4 + (lane & 3);
                const int j  = 16 * (kf & 3) + (kf >> 2);
                vals[e4] = tf32r(Tb[n * 68 + j]);
            }
            *(float4*)(dst + g) = make_float4(vals[0], vals[1], vals[2], vals[3]);
        }
    }
}

// ---------------- Kernel 2b: pack (adj + eye) != 0 into bitmask, MLP=8 ----------
__global__ __launch_bounds__(256) void k_pack(const int* __restrict__ adj) {
    const int lane = threadIdx.x & 31;
    const int gw   = (blockIdx.x * 256 + threadIdx.x) >> 5;
    const int nw   = (gridDim.x * 256) >> 5;
    for (int t = gw * 8; t < NN * 256; t += nw * 8) {
        const int* p = adj + (size_t)t * 32 + lane;
        int v[8];
        #pragma unroll
        for (int u = 0; u < 8; ++u) v[u] = p[u * 32];
        unsigned int b[8];
        #pragma unroll
        for (int u = 0; u < 8; ++u) b[u] = __ballot_sync(0xffffffffu, v[u] != 0);
        if (lane == 0) {
            #pragma unroll
            for (int u = 0; u < 8; ++u) {
                const int w = t + u, row = w >> 8, c = w & 255;
                if ((row >> 5) == c) b[u] |= 1u << (row & 31);
            }
            *(uint4*)(g_keep + t)     = make_uint4(b[0], b[1], b[2], b[3]);
            *(uint4*)(g_keep + t + 4) = make_uint4(b[4], b[5], b[6], b[7]);
        }
    }
}

// ---------------- Kernel 3: fused aggregation, barrier-free, LDG.128 fragments --
// 256 threads = 8 warps x 32 rows, all 64 N cols per warp. All chunk loads
// front-batched (12 factor LDG.128 + kw prefetch); B fragments as 8 LDG.128/kp.
__global__ __launch_bounds__(256, 1) void k_gat(float* __restrict__ out) {
    const int tid  = threadIdx.x;
    const int lane = tid & 31;
    const int wm   = tid >> 5;
    const int h    = blockIdx.x;
    const int i0   = blockIdx.y * 256;
    const int q    = lane & 3;
    const int rl   = lane >> 2;
    const unsigned int ONE = 0x3F800000u;   // 1.0f (exact in tf32)

    // rows this lane generates weights for: t = m*2+p -> row wm*32 + m*16 + p*8 + rl
    float nslR[4], qR[4];
    int growL[4];
    #pragma unroll
    for (int t = 0; t < 4; ++t) {
        const int m = t >> 1, p = t & 1;
        growL[t] = i0 + wm * 32 + m * 16 + p * 8 + rl;
        nslR[t] = g_nsl[h * NN + growL[t]];
        qR[t]   = g_q  [h * NN + growL[t]];
    }
    const unsigned int shift = (unsigned int)((q & 1) * 16);

    const float* fF   = g_hF + (size_t)h * 128 * 4096;
    const float* erG  = g_er  + h * NN;
    const float* er2G = g_er2 + h * NN;
    const float* srG  = g_sr  + h * NN;

    float acc[2][8][4];
    #pragma unroll
    for (int m = 0; m < 2; ++m)
        #pragma unroll
        for (int nt = 0; nt < 8; ++nt)
            #pragma unroll
            for (int c = 0; c < 4; ++c) acc[m][nt][c] = 0.f;
    float accD[2][4];
    #pragma unroll
    for (int m = 0; m < 2; ++m)
        #pragma unroll
        for (int c = 0; c < 4; ++c) accD[m][c] = 0.f;

    // prefetched keep words for chunk 0
    unsigned int kwP[4];
    #pragma unroll
    for (int t = 0; t < 4; ++t)
        kwP[t] = g_keep[(size_t)growL[t] * 256 + (q >> 1)];

    for (int jt = 0; jt < 128; ++jt) {
        const float* fC = fF + (size_t)jt * 4096;

        // current keep words (from prefetch)
        unsigned int kw[4];
        #pragma unroll
        for (int t = 0; t < 4; ++t) kw[t] = kwP[t] >> shift;

        // front-batch all 12 factor loads for this chunk (MLP)
        float4 erA[4], er2A[4], srA[4];
        #pragma unroll
        for (int kp = 0; kp < 4; ++kp) {
            erA[kp]  = *(const float4*)(erG  + jt * 64 + q * 16 + kp * 4);
            er2A[kp] = *(const float4*)(er2G + jt * 64 + q * 16 + kp * 4);
            srA[kp]  = *(const float4*)(srG  + jt * 64 + q * 16 + kp * 4);
        }
        // prefetch next chunk's keep words
        if (jt < 127) {
            #pragma unroll
            for (int t = 0; t < 4; ++t)
                kwP[t] = g_keep[(size_t)growL[t] * 256 + (jt + 1) * 2 + (q >> 1)];
        }

        #pragma unroll
        for (int kp = 0; kp < 4; ++kp) {
            // B fragments: 8 coalesced LDG.128 (L1-shared across warps)
            float2 bf[2][8];
            #pragma unroll
            for (int sub = 0; sub < 2; ++sub)
                #pragma unroll
                for (int nt2 = 0; nt2 < 4; ++nt2) {
                    float4 v = *(const float4*)(fC + (((kp * 2 + sub) * 4 + nt2) * 32 + lane) * 4);
                    bf[sub][nt2 * 2]     = make_float2(v.x, v.y);
                    bf[sub][nt2 * 2 + 1] = make_float2(v.z, v.w);
                }

            const float4 er4  = erA[kp];
            const float4 er24 = er2A[kp];
            const float4 sr4  = srA[kp];

            #pragma unroll
            for (int sub = 0; sub < 2; ++sub) {
                const int s = kp * 2 + sub;
                const float ex  = sub ? er4.z  : er4.x;
                const float ey  = sub ? er4.w  : er4.y;
                const float e2x = sub ? er24.z : er24.x;
                const float e2y = sub ? er24.w : er24.y;
                const float sx  = sub ? sr4.z  : sr4.x;
                const float sy  = sub ? sr4.w  : sr4.y;
                unsigned int a[2][4];
                #pragma unroll
                for (int m = 0; m < 2; ++m) {
                    #pragma unroll
                    for (int p = 0; p < 2; ++p) {
                        const int t = m * 2 + p;
                        const unsigned int bits = (kw[t] >> (2 * s)) & 3u;
                        float w0 = (sx > nslR[t]) ? qR[t] * ex : e2x;
                        float w1 = (sy > nslR[t]) ? qR[t] * ey : e2y;
                        w0 = (bits & 1u) ? w0 : 0.f;
                        w1 = (bits & 2u) ? w1 : 0.f;
                        a[m][p]     = __float_as_uint(w0);
                        a[m][p + 2] = __float_as_uint(w1);
                    }
                }
                #pragma unroll
                for (int m = 0; m < 2; ++m) {
                    #pragma unroll
                    for (int nt = 0; nt < 8; ++nt)
                        mma_tf32(acc[m][nt], a[m],
                                 __float_as_uint(bf[sub][nt].x),
                                 __float_as_uint(bf[sub][nt].y));
                    mma_tf32(accD[m], a[m], ONE, ONE);   // denominator row-sums
                }
            }
        }
    }

    // ---- epilogue: normalize + store (denominators already per-row in accD) ----
    #pragma unroll
    for (int m = 0; m < 2; ++m) {
        const int r0 = i0 + wm * 32 + m * 16 + rl;
        const float inv0 = 1.0f / accD[m][0];    // row m*16 + rl
        const float inv1 = 1.0f / accD[m][2];    // row m*16 + rl + 8
        #pragma unroll
        for (int nt = 0; nt < 8; ++nt) {
            const int c = h * ND + nt * 8 + q * 2;
            float2 v0 = make_float2(acc[m][nt][0] * inv0, acc[m][nt][1] * inv0);
            float2 v1 = make_float2(acc[m][nt][2] * inv1, acc[m][nt][3] * inv1);
            *(float2*)(out + (size_t)r0 * HD + c)       = v0;
            *(float2*)(out + (size_t)(r0 + 8) * HD + c) = v1;
        }
    }
}

// ---------------- launch ----------------
extern "C" void kernel_launch(void* const* d_in, const int* in_sizes, int n_in,
                              void* d_out, int out_size) {
    const float* x   = (const float*)d_in[0];
    const int*   adj = (const int*)  d_in[1];
    const float* W   = (const float*)d_in[2];
    const float* a_l = (const float*)d_in[3];
    const float* a_r = (const float*)d_in[4];
    float* out = (float*)d_out;

    k_pack<<<1184, 256>>>(adj);
    k_proj<<<dim3(NH, NN / 64), 256>>>(x, W, a_l, a_r);

    k_gat<<<dim3(NH, NN / 256), 256>>>(out);
}